// round 13
// baseline (speedup 1.0000x reference)
#include <cuda_runtime.h>
#include <cuda_fp16.h>

// Problem shapes (fixed by setup_inputs)
#define BN 64
#define VN 64
#define DN 64
#define HN 64
#define EN 4032     // V*(V-1)
#define ETN 2
#define OUTC (DN + HN)   // 128

// Node-factored first layer, stored FP16:
//   g_Ah[b][v][h] = fp16( b1[1][h] + sum_d in[b][v][d]*W1[1][h][d] )
//   g_Bh[b][v][h] = fp16(            sum_d in[b][v][d]*W1[1][h][DN+d] )
__device__ __half g_Ah[BN * VN * HN];
__device__ __half g_Bh[BN * VN * HN];

__device__ __forceinline__ void cp16(unsigned dst_smem, const void* src) {
    asm volatile("cp.async.ca.shared.global [%0], [%1], 16;"
                 :: "r"(dst_smem), "l"(src));
}
__device__ __forceinline__ unsigned hadd2u(unsigned a, unsigned b) {
    __half2 r = __hadd2(*reinterpret_cast<__half2*>(&a),
                        *reinterpret_cast<__half2*>(&b));
    return *reinterpret_cast<unsigned*>(&r);
}
__device__ __forceinline__ unsigned relu2u(unsigned a) {
    __half2 z = __half2half2(__ushort_as_half(0));
    __half2 r = __hmax2(*reinterpret_cast<__half2*>(&a), z);
    return *reinterpret_cast<unsigned*>(&r);
}

// ---------------------------------------------------------------------------
// Kernel 1: node-factored layer-1 precompute (fp32 math, fp16 store) +
// output init (inputs copy into [0:64], zeros into [64:128] for atomics).
// grid (BN, 4): block = 16 nodes; 256 threads, 1x4 micro-tile.
// ---------------------------------------------------------------------------
__global__ __launch_bounds__(256)
void precompute_kernel(const float* __restrict__ inp,
                       const float* __restrict__ W1,
                       const float* __restrict__ b1,
                       float* __restrict__ out) {
    __shared__ __align__(16) float W1r[DN][68];
    __shared__ __align__(16) float W1s[DN][68];

    int b   = blockIdx.x;
    int v0  = blockIdx.y * 16;
    int tid = threadIdx.x;
    const float* inb = inp + b * VN * DN;

    for (int idx = tid; idx < 16 * DN; idx += 256) {
        int v = v0 + (idx >> 6), d = idx & 63;
        float* o = out + ((size_t)(b * VN + v)) * OUTC;
        o[d]      = inb[v * DN + d];
        o[DN + d] = 0.0f;                 // zero agg half for atomic accumulation
    }
    const float* W1e = W1 + HN * 2 * DN;  // edge type 1
    for (int idx = tid; idx < HN * 2 * DN; idx += 256) {
        int h = idx >> 7, d = idx & 127;
        float w = W1e[idx];
        if (d < DN) W1r[d][h] = w;
        else        W1s[d - DN][h] = w;
    }
    __syncthreads();

    int ty = tid >> 4;          // node v0+ty (16 nodes)
    int tx = tid & 15;          // h cols 4*tx..4*tx+3
    int v  = v0 + ty;

    float acc1[4] = {0.f, 0.f, 0.f, 0.f};
    float acc2[4] = {0.f, 0.f, 0.f, 0.f};

    #pragma unroll 8
    for (int d = 0; d < DN; d++) {
        float xv = inb[v * DN + d];
        float4 wr = *(const float4*)&W1r[d][4 * tx];
        float4 ws = *(const float4*)&W1s[d][4 * tx];
        acc1[0] += xv * wr.x;  acc1[1] += xv * wr.y;
        acc1[2] += xv * wr.z;  acc1[3] += xv * wr.w;
        acc2[0] += xv * ws.x;  acc2[1] += xv * ws.y;
        acc2[2] += xv * ws.z;  acc2[3] += xv * ws.w;
    }

    // Pack 4 halfs -> one 8B store per table
    __half2 pa0 = __floats2half2_rn(acc1[0] + b1[HN + 4 * tx],
                                    acc1[1] + b1[HN + 4 * tx + 1]);
    __half2 pa1 = __floats2half2_rn(acc1[2] + b1[HN + 4 * tx + 2],
                                    acc1[3] + b1[HN + 4 * tx + 3]);
    __half2 pb0 = __floats2half2_rn(acc2[0], acc2[1]);
    __half2 pb1 = __floats2half2_rn(acc2[2], acc2[3]);
    size_t base = (size_t)(b * VN + v) * HN + 4 * tx;
    uint2 ua, ub;
    ua.x = *reinterpret_cast<unsigned*>(&pa0);
    ua.y = *reinterpret_cast<unsigned*>(&pa1);
    ub.x = *reinterpret_cast<unsigned*>(&pb0);
    ub.y = *reinterpret_cast<unsigned*>(&pb1);
    *reinterpret_cast<uint2*>(&g_Ah[base]) = ua;
    *reinterpret_cast<uint2*>(&g_Bh[base]) = ub;
}

// ---------------------------------------------------------------------------
// Kernel 2: all-fp16 m16n8k16 transposed-GEMM edge MLP, 4 blocks/SM.
// Identical machinery to R12 (fp16 node tables, swizzled LDS.128 B-builds,
// double-buffered cp.async, RED.F32 sender-half combine) with the register
// budget trimmed to fit __launch_bounds__(256,4):
//   - bias values read from L1-hot b2 in the epilogue (not registers)
//   - 512 blocks / (4/SM * 148 SM = 592) -> SINGLE WAVE, 32 warps/SM.
// ---------------------------------------------------------------------------
__global__ __launch_bounds__(256, 4)
void edge_mma_kernel(const float* __restrict__ edges,
                     const float* __restrict__ W2,
                     const float* __restrict__ b2,
                     float* __restrict__ out) {
    __shared__ __align__(16) __half Bh[2][4096];   // 2 x [64 rows][64 halfs], swizzled
    __shared__ __align__(16) __half Ah[2][128];    // 2 x [2 recv][64 halfs]
    __shared__ float wva[4 * 128];                 // edge weights, 4 batches

    int bbase = blockIdx.y * 4;
    int rbase = blockIdx.x * 2;
    int tid   = threadIdx.x;
    int w     = tid >> 5;
    int l     = tid & 31;
    int gid   = l >> 2;        // lane row-group
    int ctid  = l & 3;         // lane k-group
    int oh    = w & 1;
    int sh    = (w >> 1) & 1;
    int rl    = w >> 2;
    int obase = oh * 32;

    unsigned bhA = (unsigned)__cvta_generic_to_shared(&Bh[0][0]);
    unsigned ahA = (unsigned)__cvta_generic_to_shared(&Ah[0][0]);

    // --- cp.async batch 0 -> Bh[0] (16B chunks, slot = c ^ (s&7)) ---
    {
        const __half* src = g_Bh + (size_t)bbase * VN * HN;
        #pragma unroll
        for (int t = 0; t < 2; t++) {
            int c = tid + t * 256;            // chunk id 0..511
            int s = c >> 3, q = c & 7;
            int slot = q ^ (s & 7);
            cp16(bhA + s * 128 + slot * 16, src + c * 8);
        }
        if (tid < 16)
            cp16(ahA + tid * 16,
                 g_Ah + ((size_t)(bbase * VN + rbase)) * HN + tid * 8);
        asm volatile("cp.async.commit_group;");
    }

    // --- Stage W2[1] as fp16 into Bh[1] (linear [o][k], 8KB) ---
    {
        const float* W2e = W2 + HN * HN;
        __half* Wh = Bh[1];
        for (int idx = tid; idx < HN * HN; idx += 256)
            Wh[idx] = __float2half_rn(W2e[idx]);
    }

    // --- 4 batches of edge weights (closed-form e(s,r) = s*63 + r - (r>s)) ---
    for (int idx = tid; idx < 512; idx += 256) {
        int bi = idx >> 7, row = idx & 127;
        int srl = row >> 6, s = row & 63;
        int r = rbase + srl;
        float wgt = 0.f;
        if (s != r) {
            int e = s * 63 + r - (r > s ? 1 : 0);
            wgt = edges[((size_t)((bbase + bi) * EN + e)) * ETN + 1];
        }
        wva[idx] = wgt;
    }
    __syncthreads();

    // --- W2 A-fragments (fp16) from Bh[1]; permuted phys k = ctid*16+ms*4+{0..3}
    unsigned a0f[4][4], a1f[4][4];
    {
        const __half* Wh = Bh[1];
        int r0 = obase + gid;
        #pragma unroll
        for (int ms = 0; ms < 4; ms++) {
            int p = ctid * 16 + ms * 4;
            a0f[ms][0] = *(const unsigned*)&Wh[r0 * 64 + p];
            a0f[ms][2] = *(const unsigned*)&Wh[r0 * 64 + p + 2];
            a0f[ms][1] = *(const unsigned*)&Wh[(r0 + 8) * 64 + p];
            a0f[ms][3] = *(const unsigned*)&Wh[(r0 + 8) * 64 + p + 2];
            a1f[ms][0] = *(const unsigned*)&Wh[(r0 + 16) * 64 + p];
            a1f[ms][2] = *(const unsigned*)&Wh[(r0 + 16) * 64 + p + 2];
            a1f[ms][1] = *(const unsigned*)&Wh[(r0 + 24) * 64 + p];
            a1f[ms][3] = *(const unsigned*)&Wh[(r0 + 24) * 64 + p + 2];
        }
    }

    int buf = 0;
    for (int bi = 0; bi < 4; bi++) {
        asm volatile("cp.async.wait_group 0;");
        __syncthreads();
        // batch bi in Bh[buf]/Ah[buf]; everyone done with buf^1
        // (at bi==0 that includes the W2 fragment extraction above).

        if (bi < 3) {
            const __half* src = g_Bh + (size_t)(bbase + bi + 1) * VN * HN;
            unsigned dstB = bhA + (buf ^ 1) * 8192;
            #pragma unroll
            for (int t = 0; t < 2; t++) {
                int c = tid + t * 256;
                int s = c >> 3, q = c & 7;
                int slot = q ^ (s & 7);
                cp16(dstB + s * 128 + slot * 16, src + c * 8);
            }
            if (tid < 16)
                cp16(ahA + (buf ^ 1) * 256 + tid * 16,
                     g_Ah + ((size_t)((bbase + bi + 1) * VN + rbase)) * HN + tid * 8);
            asm volatile("cp.async.commit_group;");
        }

        // A cache: 16 halfs (phys k run) = 2x LDS.128 broadcast
        unsigned aa[8];
        {
            const __half* Ar = Ah[buf] + rl * 64 + ctid * 16;
            uint4 la0 = *(const uint4*)&Ar[0];
            uint4 la1 = *(const uint4*)&Ar[8];
            aa[0] = la0.x; aa[1] = la0.y; aa[2] = la0.z; aa[3] = la0.w;
            aa[4] = la1.x; aa[5] = la1.y; aa[6] = la1.z; aa[7] = la1.w;
        }

        float pa[2][2] = {{0.f, 0.f}, {0.f, 0.f}};
        const float* wvb = wva + bi * 128 + rl * 64;
        #pragma unroll
        for (int j = 0; j < 4; j++) {
            int nt = sh * 4 + j;
            int s  = nt * 8 + gid;
            const __half* srow = Bh[buf] + s * 64;
            int c0 = (2 * ctid)     ^ (s & 7);
            int c1 = (2 * ctid + 1) ^ (s & 7);
            uint4 lb0 = *(const uint4*)&srow[c0 * 8];   // phys k ctid*16+0..7  (ms 0,1)
            uint4 lb1 = *(const uint4*)&srow[c1 * 8];   // phys k ctid*16+8..15 (ms 2,3)
            unsigned bb[8] = {lb0.x, lb0.y, lb0.z, lb0.w,
                              lb1.x, lb1.y, lb1.z, lb1.w};

            float c0a[4] = {0.f, 0.f, 0.f, 0.f};
            float c1a[4] = {0.f, 0.f, 0.f, 0.f};
            #pragma unroll
            for (int ms = 0; ms < 4; ms++) {
                unsigned ub0 = relu2u(hadd2u(aa[2 * ms],     bb[2 * ms]));
                unsigned ub1 = relu2u(hadd2u(aa[2 * ms + 1], bb[2 * ms + 1]));
                asm volatile(
                    "mma.sync.aligned.m16n8k16.row.col.f32.f16.f16.f32 "
                    "{%0,%1,%2,%3}, {%4,%5,%6,%7}, {%8,%9}, {%0,%1,%2,%3};"
                    : "+f"(c0a[0]), "+f"(c0a[1]), "+f"(c0a[2]), "+f"(c0a[3])
                    : "r"(a0f[ms][0]), "r"(a0f[ms][1]),
                      "r"(a0f[ms][2]), "r"(a0f[ms][3]),
                      "r"(ub0), "r"(ub1));
                asm volatile(
                    "mma.sync.aligned.m16n8k16.row.col.f32.f16.f16.f32 "
                    "{%0,%1,%2,%3}, {%4,%5,%6,%7}, {%8,%9}, {%0,%1,%2,%3};"
                    : "+f"(c1a[0]), "+f"(c1a[1]), "+f"(c1a[2]), "+f"(c1a[3])
                    : "r"(a1f[ms][0]), "r"(a1f[ms][1]),
                      "r"(a1f[ms][2]), "r"(a1f[ms][3]),
                      "r"(ub0), "r"(ub1));
            }
            // Epilogue: bias from L1-hot global (saves 4 permanent registers)
            int scol = nt * 8 + 2 * ctid;
            float w0 = wvb[scol], w1 = wvb[scol + 1];
            const float* b2e = b2 + HN + obase + gid;
            float bi00 = b2e[0], bi01 = b2e[8], bi10 = b2e[16], bi11 = b2e[24];
            pa[0][0] += w0 * fmaxf(c0a[0] + bi00, 0.f)
                      + w1 * fmaxf(c0a[1] + bi00, 0.f);
            pa[0][1] += w0 * fmaxf(c0a[2] + bi01, 0.f)
                      + w1 * fmaxf(c0a[3] + bi01, 0.f);
            pa[1][0] += w0 * fmaxf(c1a[0] + bi10, 0.f)
                      + w1 * fmaxf(c1a[1] + bi10, 0.f);
            pa[1][1] += w0 * fmaxf(c1a[2] + bi11, 0.f)
                      + w1 * fmaxf(c1a[3] + bi11, 0.f);
        }
        // Reduce over the 4 sender-pair lane-groups
        #pragma unroll
        for (int ot = 0; ot < 2; ot++)
            #pragma unroll
            for (int hf = 0; hf < 2; hf++) {
                pa[ot][hf] += __shfl_xor_sync(0xFFFFFFFFu, pa[ot][hf], 1);
                pa[ot][hf] += __shfl_xor_sync(0xFFFFFFFFu, pa[ot][hf], 2);
            }
        // Combine sender halves via RED.F32 into zero-initialized output
        if (ctid == 0) {
            float* dst = out + ((size_t)((bbase + bi) * VN + rbase + rl)) * OUTC
                       + DN + obase;
            atomicAdd(&dst[gid],      pa[0][0]);
            atomicAdd(&dst[gid + 8],  pa[0][1]);
            atomicAdd(&dst[gid + 16], pa[1][0]);
            atomicAdd(&dst[gid + 24], pa[1][1]);
        }
        buf ^= 1;
    }
}

// ---------------------------------------------------------------------------
// Launch
// ---------------------------------------------------------------------------
extern "C" void kernel_launch(void* const* d_in, const int* in_sizes, int n_in,
                              void* d_out, int out_size) {
    const float* inputs = (const float*)d_in[0];
    const float* edges  = (const float*)d_in[1];
    const float* W1     = (const float*)d_in[2];
    const float* b1     = (const float*)d_in[3];
    const float* W2     = (const float*)d_in[4];
    const float* b2     = (const float*)d_in[5];
    float* out = (float*)d_out;

    {
        dim3 grid(BN, 4);    // 256 blocks, 16 nodes each
        precompute_kernel<<<grid, 256>>>(inputs, W1, b1, out);
    }
    {
        dim3 grid(VN / 2, BN / 4);   // 32 x 16 = 512 blocks, 4/SM -> one wave
        edge_mma_kernel<<<grid, 256>>>(edges, W2, b2, out);
    }
}

// round 14
// speedup vs baseline: 1.1261x; 1.1261x over previous
#include <cuda_runtime.h>
#include <cuda_fp16.h>

// Problem shapes (fixed by setup_inputs)
#define BN 64
#define VN 64
#define DN 64
#define HN 64
#define EN 4032     // V*(V-1)
#define ETN 2
#define OUTC (DN + HN)   // 128
#define GY 13            // batch groups (grid.y): 416 blocks <= 444 capacity

// Node-factored first layer, stored FP16:
//   g_Ah[b][v][h] = fp16( b1[1][h] + sum_d in[b][v][d]*W1[1][h][d] )
//   g_Bh[b][v][h] = fp16(            sum_d in[b][v][d]*W1[1][h][DN+d] )
__device__ __half g_Ah[BN * VN * HN];
__device__ __half g_Bh[BN * VN * HN];

__device__ __forceinline__ void cp16(unsigned dst_smem, const void* src) {
    asm volatile("cp.async.ca.shared.global [%0], [%1], 16;"
                 :: "r"(dst_smem), "l"(src));
}
__device__ __forceinline__ unsigned hadd2u(unsigned a, unsigned b) {
    __half2 r = __hadd2(*reinterpret_cast<__half2*>(&a),
                        *reinterpret_cast<__half2*>(&b));
    return *reinterpret_cast<unsigned*>(&r);
}
__device__ __forceinline__ unsigned relu2u(unsigned a) {
    __half2 z = __half2half2(__ushort_as_half(0));
    __half2 r = __hmax2(*reinterpret_cast<__half2*>(&a), z);
    return *reinterpret_cast<unsigned*>(&r);
}

// ---------------------------------------------------------------------------
// Kernel 1: node-factored layer-1 precompute (fp32 math, fp16 store).
// NO output writes anymore (edge kernel owns all of `out`).
// grid (BN, 4): block = 16 nodes; 256 threads, 1x4 micro-tile.
// ---------------------------------------------------------------------------
__global__ __launch_bounds__(256)
void precompute_kernel(const float* __restrict__ inp,
                       const float* __restrict__ W1,
                       const float* __restrict__ b1) {
    __shared__ __align__(16) float W1r[DN][68];
    __shared__ __align__(16) float W1s[DN][68];

    int b   = blockIdx.x;
    int v0  = blockIdx.y * 16;
    int tid = threadIdx.x;
    const float* inb = inp + b * VN * DN;

    const float* W1e = W1 + HN * 2 * DN;  // edge type 1
    for (int idx = tid; idx < HN * 2 * DN; idx += 256) {
        int h = idx >> 7, d = idx & 127;
        float w = W1e[idx];
        if (d < DN) W1r[d][h] = w;
        else        W1s[d - DN][h] = w;
    }
    __syncthreads();

    int ty = tid >> 4;          // node v0+ty (16 nodes)
    int tx = tid & 15;          // h cols 4*tx..4*tx+3
    int v  = v0 + ty;

    float acc1[4] = {0.f, 0.f, 0.f, 0.f};
    float acc2[4] = {0.f, 0.f, 0.f, 0.f};

    #pragma unroll 8
    for (int d = 0; d < DN; d++) {
        float xv = inb[v * DN + d];
        float4 wr = *(const float4*)&W1r[d][4 * tx];
        float4 ws = *(const float4*)&W1s[d][4 * tx];
        acc1[0] += xv * wr.x;  acc1[1] += xv * wr.y;
        acc1[2] += xv * wr.z;  acc1[3] += xv * wr.w;
        acc2[0] += xv * ws.x;  acc2[1] += xv * ws.y;
        acc2[2] += xv * ws.z;  acc2[3] += xv * ws.w;
    }

    __half2 pa0 = __floats2half2_rn(acc1[0] + b1[HN + 4 * tx],
                                    acc1[1] + b1[HN + 4 * tx + 1]);
    __half2 pa1 = __floats2half2_rn(acc1[2] + b1[HN + 4 * tx + 2],
                                    acc1[3] + b1[HN + 4 * tx + 3]);
    __half2 pb0 = __floats2half2_rn(acc2[0], acc2[1]);
    __half2 pb1 = __floats2half2_rn(acc2[2], acc2[3]);
    size_t base = (size_t)(b * VN + v) * HN + 4 * tx;
    uint2 ua, ub;
    ua.x = *reinterpret_cast<unsigned*>(&pa0);
    ua.y = *reinterpret_cast<unsigned*>(&pa1);
    ub.x = *reinterpret_cast<unsigned*>(&pb0);
    ub.y = *reinterpret_cast<unsigned*>(&pb1);
    *reinterpret_cast<uint2*>(&g_Ah[base]) = ua;
    *reinterpret_cast<uint2*>(&g_Bh[base]) = ub;
}

// ---------------------------------------------------------------------------
// Kernel 2: all-fp16 m16n8k16 transposed-GEMM edge MLP, single-wave grid.
// Block = (2 receivers) x (4-5 batches); grid 32 x 13 = 416 <= 444 capacity
// at 3 blocks/SM -> no wave tail. Batch range: [(y*BN)/GY, ((y+1)*BN)/GY).
// R12 machinery: fp16 node tables, swizzled LDS.128 B-builds, double-buffered
// cp.async, bias in registers. Sender halves combine via double-buffered
// smem P (no atomics) -> plain stores; the out[0:64] inputs-copy rides along.
// ---------------------------------------------------------------------------
__global__ __launch_bounds__(256, 3)
void edge_mma_kernel(const float* __restrict__ inputs,
                     const float* __restrict__ edges,
                     const float* __restrict__ W2,
                     const float* __restrict__ b2,
                     float* __restrict__ out) {
    __shared__ __align__(16) __half Bh[2][4096];   // 2 x [64 rows][64 halfs], swizzled
    __shared__ __align__(16) __half Ah[2][128];    // 2 x [2 recv][64 halfs]
    __shared__ float wva[5 * 128];                 // edge weights, up to 5 batches
    __shared__ float P[2 * 256];                   // double-buffered sender partials

    int s0    = (blockIdx.y * BN) / GY;            // first batch
    int nb    = ((blockIdx.y + 1) * BN) / GY - s0; // 4 or 5 batches
    int rbase = blockIdx.x * 2;
    int tid   = threadIdx.x;
    int w     = tid >> 5;
    int l     = tid & 31;
    int gid   = l >> 2;        // lane row-group
    int ctid  = l & 3;         // lane k-group
    int oh    = w & 1;
    int sh    = (w >> 1) & 1;
    int rl    = w >> 2;
    int obase = oh * 32;

    unsigned bhA = (unsigned)__cvta_generic_to_shared(&Bh[0][0]);
    unsigned ahA = (unsigned)__cvta_generic_to_shared(&Ah[0][0]);

    // --- cp.async batch s0 -> Bh[0] (16B chunks, slot = c ^ (s&7)) ---
    {
        const __half* src = g_Bh + (size_t)s0 * VN * HN;
        #pragma unroll
        for (int t = 0; t < 2; t++) {
            int c = tid + t * 256;            // chunk id 0..511
            int s = c >> 3, q = c & 7;
            int slot = q ^ (s & 7);
            cp16(bhA + s * 128 + slot * 16, src + c * 8);
        }
        if (tid < 16)
            cp16(ahA + tid * 16,
                 g_Ah + ((size_t)(s0 * VN + rbase)) * HN + tid * 8);
        asm volatile("cp.async.commit_group;");
    }

    // --- Stage W2[1] as fp16 into Bh[1] (linear [o][k], 8KB) ---
    {
        const float* W2e = W2 + HN * HN;
        __half* Wh = Bh[1];
        for (int idx = tid; idx < HN * HN; idx += 256)
            Wh[idx] = __float2half_rn(W2e[idx]);
    }

    // --- nb batches of edge weights (closed-form e(s,r) = s*63 + r - (r>s)) ---
    for (int idx = tid; idx < nb * 128; idx += 256) {
        int bi = idx >> 7, row = idx & 127;
        int srl = row >> 6, s = row & 63;
        int r = rbase + srl;
        float wgt = 0.f;
        if (s != r) {
            int e = s * 63 + r - (r > s ? 1 : 0);
            wgt = edges[((size_t)((s0 + bi) * EN + e)) * ETN + 1];
        }
        wva[idx] = wgt;
    }
    __syncthreads();

    // --- W2 A-fragments (fp16) from Bh[1]; permuted phys k = ctid*16+ms*4+{0..3}
    unsigned a0f[4][4], a1f[4][4];
    float bias[2][2];
    {
        const __half* Wh = Bh[1];
        int r0 = obase + gid;
        #pragma unroll
        for (int ms = 0; ms < 4; ms++) {
            int p = ctid * 16 + ms * 4;
            a0f[ms][0] = *(const unsigned*)&Wh[r0 * 64 + p];
            a0f[ms][2] = *(const unsigned*)&Wh[r0 * 64 + p + 2];
            a0f[ms][1] = *(const unsigned*)&Wh[(r0 + 8) * 64 + p];
            a0f[ms][3] = *(const unsigned*)&Wh[(r0 + 8) * 64 + p + 2];
            a1f[ms][0] = *(const unsigned*)&Wh[(r0 + 16) * 64 + p];
            a1f[ms][2] = *(const unsigned*)&Wh[(r0 + 16) * 64 + p + 2];
            a1f[ms][1] = *(const unsigned*)&Wh[(r0 + 24) * 64 + p];
            a1f[ms][3] = *(const unsigned*)&Wh[(r0 + 24) * 64 + p + 2];
        }
        bias[0][0] = b2[HN + obase + gid];
        bias[0][1] = b2[HN + obase + 8 + gid];
        bias[1][0] = b2[HN + obase + 16 + gid];
        bias[1][1] = b2[HN + obase + 24 + gid];
    }

    int buf = 0;
    for (int bi = 0; bi < nb; bi++) {
        asm volatile("cp.async.wait_group 0;");
        __syncthreads();
        // batch s0+bi in Bh[buf]/Ah[buf]; everyone done with buf^1
        // (at bi==0 that includes the W2 fragment extraction above);
        // P[(bi-1)&1] complete.

        // Store previous batch's agg output + inputs copy (plain stores)
        if (bi > 0 && tid < 128) {
            int srl = tid >> 6, o = tid & 63;
            int bprev = s0 + bi - 1;
            size_t row = (size_t)(bprev * VN + rbase + srl);
            const float* Pp = P + ((bi - 1) & 1) * 256 + srl * 128;
            out[row * OUTC + DN + o] = Pp[o] + Pp[64 + o];
            out[row * OUTC + o]      = inputs[row * DN + o];
        }

        if (bi < nb - 1) {
            const __half* src = g_Bh + (size_t)(s0 + bi + 1) * VN * HN;
            unsigned dstB = bhA + (buf ^ 1) * 8192;
            #pragma unroll
            for (int t = 0; t < 2; t++) {
                int c = tid + t * 256;
                int s = c >> 3, q = c & 7;
                int slot = q ^ (s & 7);
                cp16(dstB + s * 128 + slot * 16, src + c * 8);
            }
            if (tid < 16)
                cp16(ahA + (buf ^ 1) * 256 + tid * 16,
                     g_Ah + ((size_t)((s0 + bi + 1) * VN + rbase)) * HN + tid * 8);
            asm volatile("cp.async.commit_group;");
        }

        // A cache: 16 halfs (phys k run) = 2x LDS.128 broadcast
        unsigned aa[8];
        {
            const __half* Ar = Ah[buf] + rl * 64 + ctid * 16;
            uint4 la0 = *(const uint4*)&Ar[0];
            uint4 la1 = *(const uint4*)&Ar[8];
            aa[0] = la0.x; aa[1] = la0.y; aa[2] = la0.z; aa[3] = la0.w;
            aa[4] = la1.x; aa[5] = la1.y; aa[6] = la1.z; aa[7] = la1.w;
        }

        float pa[2][2] = {{0.f, 0.f}, {0.f, 0.f}};
        const float* wvb = wva + bi * 128 + rl * 64;
        #pragma unroll
        for (int j = 0; j < 4; j++) {
            int nt = sh * 4 + j;
            int s  = nt * 8 + gid;
            const __half* srow = Bh[buf] + s * 64;
            int c0 = (2 * ctid)     ^ (s & 7);
            int c1 = (2 * ctid + 1) ^ (s & 7);
            uint4 lb0 = *(const uint4*)&srow[c0 * 8];   // phys k ctid*16+0..7  (ms 0,1)
            uint4 lb1 = *(const uint4*)&srow[c1 * 8];   // phys k ctid*16+8..15 (ms 2,3)
            unsigned bb[8] = {lb0.x, lb0.y, lb0.z, lb0.w,
                              lb1.x, lb1.y, lb1.z, lb1.w};

            float c0a[4] = {0.f, 0.f, 0.f, 0.f};
            float c1a[4] = {0.f, 0.f, 0.f, 0.f};
            #pragma unroll
            for (int ms = 0; ms < 4; ms++) {
                unsigned ub0 = relu2u(hadd2u(aa[2 * ms],     bb[2 * ms]));
                unsigned ub1 = relu2u(hadd2u(aa[2 * ms + 1], bb[2 * ms + 1]));
                asm volatile(
                    "mma.sync.aligned.m16n8k16.row.col.f32.f16.f16.f32 "
                    "{%0,%1,%2,%3}, {%4,%5,%6,%7}, {%8,%9}, {%0,%1,%2,%3};"
                    : "+f"(c0a[0]), "+f"(c0a[1]), "+f"(c0a[2]), "+f"(c0a[3])
                    : "r"(a0f[ms][0]), "r"(a0f[ms][1]),
                      "r"(a0f[ms][2]), "r"(a0f[ms][3]),
                      "r"(ub0), "r"(ub1));
                asm volatile(
                    "mma.sync.aligned.m16n8k16.row.col.f32.f16.f16.f32 "
                    "{%0,%1,%2,%3}, {%4,%5,%6,%7}, {%8,%9}, {%0,%1,%2,%3};"
                    : "+f"(c1a[0]), "+f"(c1a[1]), "+f"(c1a[2]), "+f"(c1a[3])
                    : "r"(a1f[ms][0]), "r"(a1f[ms][1]),
                      "r"(a1f[ms][2]), "r"(a1f[ms][3]),
                      "r"(ub0), "r"(ub1));
            }
            int scol = nt * 8 + 2 * ctid;
            float w0 = wvb[scol], w1 = wvb[scol + 1];
            pa[0][0] += w0 * fmaxf(c0a[0] + bias[0][0], 0.f)
                      + w1 * fmaxf(c0a[1] + bias[0][0], 0.f);
            pa[0][1] += w0 * fmaxf(c0a[2] + bias[0][1], 0.f)
                      + w1 * fmaxf(c0a[3] + bias[0][1], 0.f);
            pa[1][0] += w0 * fmaxf(c1a[0] + bias[1][0], 0.f)
                      + w1 * fmaxf(c1a[1] + bias[1][0], 0.f);
            pa[1][1] += w0 * fmaxf(c1a[2] + bias[1][1], 0.f)
                      + w1 * fmaxf(c1a[3] + bias[1][1], 0.f);
        }
        // Reduce over the 4 sender-pair lane-groups
        #pragma unroll
        for (int ot = 0; ot < 2; ot++)
            #pragma unroll
            for (int hf = 0; hf < 2; hf++) {
                pa[ot][hf] += __shfl_xor_sync(0xFFFFFFFFu, pa[ot][hf], 1);
                pa[ot][hf] += __shfl_xor_sync(0xFFFFFFFFu, pa[ot][hf], 2);
            }
        // Write this batch's partials to double-buffered P
        if (ctid == 0) {
            float* Pp = P + (bi & 1) * 256 + rl * 128 + sh * 64 + obase;
            Pp[gid]      = pa[0][0];
            Pp[gid + 8]  = pa[0][1];
            Pp[gid + 16] = pa[1][0];
            Pp[gid + 24] = pa[1][1];
        }
        buf ^= 1;
    }
    __syncthreads();
    // Final batch's stores
    if (tid < 128) {
        int srl = tid >> 6, o = tid & 63;
        int blast = s0 + nb - 1;
        size_t row = (size_t)(blast * VN + rbase + srl);
        const float* Pp = P + ((nb - 1) & 1) * 256 + srl * 128;
        out[row * OUTC + DN + o] = Pp[o] + Pp[64 + o];
        out[row * OUTC + o]      = inputs[row * DN + o];
    }
}

// ---------------------------------------------------------------------------
// Launch
// ---------------------------------------------------------------------------
extern "C" void kernel_launch(void* const* d_in, const int* in_sizes, int n_in,
                              void* d_out, int out_size) {
    const float* inputs = (const float*)d_in[0];
    const float* edges  = (const float*)d_in[1];
    const float* W1     = (const float*)d_in[2];
    const float* b1     = (const float*)d_in[3];
    const float* W2     = (const float*)d_in[4];
    const float* b2     = (const float*)d_in[5];
    float* out = (float*)d_out;

    {
        dim3 grid(BN, 4);    // 256 blocks, 16 nodes each
        precompute_kernel<<<grid, 256>>>(inputs, W1, b1);
    }
    {
        dim3 grid(VN / 2, GY);   // 32 x 13 = 416 blocks <= 444 capacity
        edge_mma_kernel<<<grid, 256>>>(inputs, edges, W2, b2, out);
    }
}

// round 15
// speedup vs baseline: 1.1336x; 1.0066x over previous
#include <cuda_runtime.h>
#include <cuda_fp16.h>

// Problem shapes (fixed by setup_inputs)
#define BN 64
#define VN 64
#define DN 64
#define HN 64
#define EN 4032     // V*(V-1)
#define ETN 2
#define OUTC (DN + HN)   // 128
#define GY 13            // batch groups (grid.y): 416 blocks <= 444 capacity

// Node-factored first layer, stored FP16:
//   g_Ah[b][v][h] = fp16( b1[1][h] + sum_d in[b][v][d]*W1[1][h][d] )
//   g_Bh[b][v][h] = fp16(            sum_d in[b][v][d]*W1[1][h][DN+d] )
__device__ __half g_Ah[BN * VN * HN];
__device__ __half g_Bh[BN * VN * HN];
// W2[1] pre-packed into m16n8k16 A-fragment layout:
//   [oh][lane][ms][8 x b32]  (first 4 = a0f[ms][0..3], next 4 = a1f[ms][0..3])
__device__ unsigned g_W2frag[2 * 32 * 4 * 8];

__device__ __forceinline__ void cp16(unsigned dst_smem, const void* src) {
    asm volatile("cp.async.ca.shared.global [%0], [%1], 16;"
                 :: "r"(dst_smem), "l"(src));
}
__device__ __forceinline__ unsigned hadd2u(unsigned a, unsigned b) {
    __half2 r = __hadd2(*reinterpret_cast<__half2*>(&a),
                        *reinterpret_cast<__half2*>(&b));
    return *reinterpret_cast<unsigned*>(&r);
}
__device__ __forceinline__ unsigned relu2u(unsigned a) {
    __half2 z = __half2half2(__ushort_as_half(0));
    __half2 r = __hmax2(*reinterpret_cast<__half2*>(&a), z);
    return *reinterpret_cast<unsigned*>(&r);
}
__device__ __forceinline__ unsigned packh2(float lo, float hi) {
    __half2 h = __floats2half2_rn(lo, hi);
    return *reinterpret_cast<unsigned*>(&h);
}

// ---------------------------------------------------------------------------
// Kernel 1: node-factored layer-1 precompute (fp32 math, fp16 store).
// Block (0,0) additionally packs W2[1] into g_W2frag (fragment layout).
// grid (BN, 4): block = 16 nodes; 256 threads, 1x4 micro-tile.
// ---------------------------------------------------------------------------
__global__ __launch_bounds__(256)
void precompute_kernel(const float* __restrict__ inp,
                       const float* __restrict__ W1,
                       const float* __restrict__ b1,
                       const float* __restrict__ W2) {
    __shared__ __align__(16) float W1r[DN][68];
    __shared__ __align__(16) float W1s[DN][68];

    int b   = blockIdx.x;
    int v0  = blockIdx.y * 16;
    int tid = threadIdx.x;
    const float* inb = inp + b * VN * DN;

    // Block (0,0): pack W2[1] fragments (independent of the rest)
    if (b == 0 && blockIdx.y == 0) {
        const float* W2e = W2 + HN * HN;   // edge type 1, [o][k]
        int ohp  = tid >> 7;               // 0/1
        int lp   = (tid >> 2) & 31;        // lane
        int msp  = tid & 3;                // k-step
        int gidp = lp >> 2, ctidp = lp & 3;
        int r0   = ohp * 32 + gidp;
        int p    = ctidp * 16 + msp * 4;
        uint4 qa, qb;
        qa.x = packh2(W2e[r0 * 64 + p],        W2e[r0 * 64 + p + 1]);
        qa.y = packh2(W2e[(r0 + 8) * 64 + p],  W2e[(r0 + 8) * 64 + p + 1]);
        qa.z = packh2(W2e[r0 * 64 + p + 2],    W2e[r0 * 64 + p + 3]);
        qa.w = packh2(W2e[(r0 + 8) * 64 + p + 2], W2e[(r0 + 8) * 64 + p + 3]);
        qb.x = packh2(W2e[(r0 + 16) * 64 + p],    W2e[(r0 + 16) * 64 + p + 1]);
        qb.y = packh2(W2e[(r0 + 24) * 64 + p],    W2e[(r0 + 24) * 64 + p + 1]);
        qb.z = packh2(W2e[(r0 + 16) * 64 + p + 2], W2e[(r0 + 16) * 64 + p + 3]);
        qb.w = packh2(W2e[(r0 + 24) * 64 + p + 2], W2e[(r0 + 24) * 64 + p + 3]);
        uint4* Wf4 = reinterpret_cast<uint4*>(g_W2frag);
        Wf4[tid * 2]     = qa;
        Wf4[tid * 2 + 1] = qb;
    }

    const float* W1e = W1 + HN * 2 * DN;  // edge type 1
    for (int idx = tid; idx < HN * 2 * DN; idx += 256) {
        int h = idx >> 7, d = idx & 127;
        float w = W1e[idx];
        if (d < DN) W1r[d][h] = w;
        else        W1s[d - DN][h] = w;
    }
    __syncthreads();

    int ty = tid >> 4;          // node v0+ty (16 nodes)
    int tx = tid & 15;          // h cols 4*tx..4*tx+3
    int v  = v0 + ty;

    float acc1[4] = {0.f, 0.f, 0.f, 0.f};
    float acc2[4] = {0.f, 0.f, 0.f, 0.f};

    #pragma unroll 8
    for (int d = 0; d < DN; d++) {
        float xv = inb[v * DN + d];
        float4 wr = *(const float4*)&W1r[d][4 * tx];
        float4 ws = *(const float4*)&W1s[d][4 * tx];
        acc1[0] += xv * wr.x;  acc1[1] += xv * wr.y;
        acc1[2] += xv * wr.z;  acc1[3] += xv * wr.w;
        acc2[0] += xv * ws.x;  acc2[1] += xv * ws.y;
        acc2[2] += xv * ws.z;  acc2[3] += xv * ws.w;
    }

    __half2 pa0 = __floats2half2_rn(acc1[0] + b1[HN + 4 * tx],
                                    acc1[1] + b1[HN + 4 * tx + 1]);
    __half2 pa1 = __floats2half2_rn(acc1[2] + b1[HN + 4 * tx + 2],
                                    acc1[3] + b1[HN + 4 * tx + 3]);
    __half2 pb0 = __floats2half2_rn(acc2[0], acc2[1]);
    __half2 pb1 = __floats2half2_rn(acc2[2], acc2[3]);
    size_t base = (size_t)(b * VN + v) * HN + 4 * tx;
    uint2 ua, ub;
    ua.x = *reinterpret_cast<unsigned*>(&pa0);
    ua.y = *reinterpret_cast<unsigned*>(&pa1);
    ub.x = *reinterpret_cast<unsigned*>(&pb0);
    ub.y = *reinterpret_cast<unsigned*>(&pb1);
    *reinterpret_cast<uint2*>(&g_Ah[base]) = ua;
    *reinterpret_cast<uint2*>(&g_Bh[base]) = ub;
}

// ---------------------------------------------------------------------------
// Kernel 2: all-fp16 m16n8k16 transposed-GEMM edge MLP.
// vs R14: W2 fragments loaded with 8 coalesced LDG.128 from g_W2frag (no
// smem staging / extraction), and the Bm/A staging is TRIPLE-buffered with
// cp.async prefetch depth 2 (wait_group 1) so per-iter load latency is
// hidden. Block = (2 receivers) x (4-5 batches); grid 32 x 13 = 416 blocks.
// ---------------------------------------------------------------------------
__device__ __forceinline__ void stage_batch(unsigned bhA, unsigned ahA,
                                            int bufIdx, int batch,
                                            int tid, int rbase) {
    const __half* src = g_Bh + (size_t)batch * VN * HN;
    unsigned dstB = bhA + bufIdx * 8192;
    #pragma unroll
    for (int t = 0; t < 2; t++) {
        int c = tid + t * 256;            // chunk id 0..511
        int s = c >> 3, q = c & 7;
        int slot = q ^ (s & 7);
        cp16(dstB + s * 128 + slot * 16, src + c * 8);
    }
    if (tid < 16)
        cp16(ahA + bufIdx * 256 + tid * 16,
             g_Ah + ((size_t)(batch * VN + rbase)) * HN + tid * 8);
    asm volatile("cp.async.commit_group;");
}

__global__ __launch_bounds__(256, 3)
void edge_mma_kernel(const float* __restrict__ inputs,
                     const float* __restrict__ edges,
                     const float* __restrict__ b2,
                     float* __restrict__ out) {
    __shared__ __align__(16) __half Bh[3][4096];   // 3 x [64 rows][64 halfs], swizzled
    __shared__ __align__(16) __half Ah[3][128];    // 3 x [2 recv][64 halfs]
    __shared__ float wva[5 * 128];                 // edge weights, up to 5 batches
    __shared__ float P[2 * 256];                   // double-buffered sender partials

    int s0    = (blockIdx.y * BN) / GY;            // first batch
    int nb    = ((blockIdx.y + 1) * BN) / GY - s0; // 4 or 5 batches
    int rbase = blockIdx.x * 2;
    int tid   = threadIdx.x;
    int w     = tid >> 5;
    int l     = tid & 31;
    int gid   = l >> 2;        // lane row-group
    int ctid  = l & 3;         // lane k-group
    int oh    = w & 1;
    int sh    = (w >> 1) & 1;
    int rl    = w >> 2;
    int obase = oh * 32;

    unsigned bhA = (unsigned)__cvta_generic_to_shared(&Bh[0][0]);
    unsigned ahA = (unsigned)__cvta_generic_to_shared(&Ah[0][0]);

    // --- Prefetch depth 2: batches s0 and s0+1 (nb >= 4 always) ---
    stage_batch(bhA, ahA, 0, s0,     tid, rbase);
    stage_batch(bhA, ahA, 1, s0 + 1, tid, rbase);

    // --- W2 A-fragments: 8 coalesced LDG.128 from pre-packed g_W2frag ---
    unsigned a0f[4][4], a1f[4][4];
    float bias[2][2];
    {
        const uint4* Wf4 = reinterpret_cast<const uint4*>(g_W2frag);
        int fbase = ((oh * 32 + l) * 4) * 2;
        #pragma unroll
        for (int ms = 0; ms < 4; ms++) {
            uint4 qa = Wf4[fbase + ms * 2];
            uint4 qb = Wf4[fbase + ms * 2 + 1];
            a0f[ms][0] = qa.x; a0f[ms][1] = qa.y;
            a0f[ms][2] = qa.z; a0f[ms][3] = qa.w;
            a1f[ms][0] = qb.x; a1f[ms][1] = qb.y;
            a1f[ms][2] = qb.z; a1f[ms][3] = qb.w;
        }
        bias[0][0] = b2[HN + obase + gid];
        bias[0][1] = b2[HN + obase + 8 + gid];
        bias[1][0] = b2[HN + obase + 16 + gid];
        bias[1][1] = b2[HN + obase + 24 + gid];
    }

    // --- nb batches of edge weights (closed-form e(s,r) = s*63 + r - (r>s)) ---
    for (int idx = tid; idx < nb * 128; idx += 256) {
        int bi = idx >> 7, row = idx & 127;
        int srl = row >> 6, s = row & 63;
        int r = rbase + srl;
        float wgt = 0.f;
        if (s != r) {
            int e = s * 63 + r - (r > s ? 1 : 0);
            wgt = edges[((size_t)((s0 + bi) * EN + e)) * ETN + 1];
        }
        wva[idx] = wgt;
    }

    int buf = 0;   // = bi % 3
    for (int bi = 0; bi < nb; bi++) {
        // Depth-2 wait: batch bi's group is complete when <=1 groups remain
        if (bi == nb - 1) asm volatile("cp.async.wait_group 0;");
        else              asm volatile("cp.async.wait_group 1;");
        __syncthreads();
        // batch s0+bi in Bh[buf]/Ah[buf]; buffer (bi+2)%3's last readers
        // (iter bi-1) are past the barrier; P[(bi-1)&1] complete; wva visible.

        // Store previous batch's agg output + inputs copy (plain stores)
        if (bi > 0 && tid < 128) {
            int srl = tid >> 6, o = tid & 63;
            int bprev = s0 + bi - 1;
            size_t row = (size_t)(bprev * VN + rbase + srl);
            const float* Pp = P + ((bi - 1) & 1) * 256 + srl * 128;
            out[row * OUTC + DN + o] = Pp[o] + Pp[64 + o];
            out[row * OUTC + o]      = inputs[row * DN + o];
        }

        // Prefetch batch bi+2 into buffer (bi+2)%3
        if (bi + 2 < nb) {
            int nxt = buf + 2; if (nxt >= 3) nxt -= 3;
            stage_batch(bhA, ahA, nxt, s0 + bi + 2, tid, rbase);
        }

        // A cache: 16 halfs (phys k run) = 2x LDS.128 broadcast
        unsigned aa[8];
        {
            const __half* Ar = Ah[buf] + rl * 64 + ctid * 16;
            uint4 la0 = *(const uint4*)&Ar[0];
            uint4 la1 = *(const uint4*)&Ar[8];
            aa[0] = la0.x; aa[1] = la0.y; aa[2] = la0.z; aa[3] = la0.w;
            aa[4] = la1.x; aa[5] = la1.y; aa[6] = la1.z; aa[7] = la1.w;
        }

        float pa[2][2] = {{0.f, 0.f}, {0.f, 0.f}};
        const float* wvb = wva + bi * 128 + rl * 64;
        #pragma unroll
        for (int j = 0; j < 4; j++) {
            int nt = sh * 4 + j;
            int s  = nt * 8 + gid;
            const __half* srow = Bh[buf] + s * 64;
            int c0 = (2 * ctid)     ^ (s & 7);
            int c1 = (2 * ctid + 1) ^ (s & 7);
            uint4 lb0 = *(const uint4*)&srow[c0 * 8];   // phys k ctid*16+0..7  (ms 0,1)
            uint4 lb1 = *(const uint4*)&srow[c1 * 8];   // phys k ctid*16+8..15 (ms 2,3)
            unsigned bb[8] = {lb0.x, lb0.y, lb0.z, lb0.w,
                              lb1.x, lb1.y, lb1.z, lb1.w};

            float c0a[4] = {0.f, 0.f, 0.f, 0.f};
            float c1a[4] = {0.f, 0.f, 0.f, 0.f};
            #pragma unroll
            for (int ms = 0; ms < 4; ms++) {
                unsigned ub0 = relu2u(hadd2u(aa[2 * ms],     bb[2 * ms]));
                unsigned ub1 = relu2u(hadd2u(aa[2 * ms + 1], bb[2 * ms + 1]));
                asm volatile(
                    "mma.sync.aligned.m16n8k16.row.col.f32.f16.f16.f32 "
                    "{%0,%1,%2,%3}, {%4,%5,%6,%7}, {%8,%9}, {%0,%1,%2,%3};"
                    : "+f"(c0a[0]), "+f"(c0a[1]), "+f"(c0a[2]), "+f"(c0a[3])
                    : "r"(a0f[ms][0]), "r"(a0f[ms][1]),
                      "r"(a0f[ms][2]), "r"(a0f[ms][3]),
                      "r"(ub0), "r"(ub1));
                asm volatile(
                    "mma.sync.aligned.m16n8k16.row.col.f32.f16.f16.f32 "
                    "{%0,%1,%2,%3}, {%4,%5,%6,%7}, {%8,%9}, {%0,%1,%2,%3};"
                    : "+f"(c1a[0]), "+f"(c1a[1]), "+f"(c1a[2]), "+f"(c1a[3])
                    : "r"(a1f[ms][0]), "r"(a1f[ms][1]),
                      "r"(a1f[ms][2]), "r"(a1f[ms][3]),
                      "r"(ub0), "r"(ub1));
            }
            int scol = nt * 8 + 2 * ctid;
            float w0 = wvb[scol], w1 = wvb[scol + 1];
            pa[0][0] += w0 * fmaxf(c0a[0] + bias[0][0], 0.f)
                      + w1 * fmaxf(c0a[1] + bias[0][0], 0.f);
            pa[0][1] += w0 * fmaxf(c0a[2] + bias[0][1], 0.f)
                      + w1 * fmaxf(c0a[3] + bias[0][1], 0.f);
            pa[1][0] += w0 * fmaxf(c1a[0] + bias[1][0], 0.f)
                      + w1 * fmaxf(c1a[1] + bias[1][0], 0.f);
            pa[1][1] += w0 * fmaxf(c1a[2] + bias[1][1], 0.f)
                      + w1 * fmaxf(c1a[3] + bias[1][1], 0.f);
        }
        // Reduce over the 4 sender-pair lane-groups
        #pragma unroll
        for (int ot = 0; ot < 2; ot++)
            #pragma unroll
            for (int hf = 0; hf < 2; hf++) {
                pa[ot][hf] += __shfl_xor_sync(0xFFFFFFFFu, pa[ot][hf], 1);
                pa[ot][hf] += __shfl_xor_sync(0xFFFFFFFFu, pa[ot][hf], 2);
            }
        // Write this batch's partials to double-buffered P
        if (ctid == 0) {
            float* Pp = P + (bi & 1) * 256 + rl * 128 + sh * 64 + obase;
            Pp[gid]      = pa[0][0];
            Pp[gid + 8]  = pa[0][1];
            Pp[gid + 16] = pa[1][0];
            Pp[gid + 24] = pa[1][1];
        }
        buf = (buf == 2) ? 0 : buf + 1;
    }
    __syncthreads();
    // Final batch's stores
    if (tid < 128) {
        int srl = tid >> 6, o = tid & 63;
        int blast = s0 + nb - 1;
        size_t row = (size_t)(blast * VN + rbase + srl);
        const float* Pp = P + ((nb - 1) & 1) * 256 + srl * 128;
        out[row * OUTC + DN + o] = Pp[o] + Pp[64 + o];
        out[row * OUTC + o]      = inputs[row * DN + o];
    }
}

// ---------------------------------------------------------------------------
// Launch
// ---------------------------------------------------------------------------
extern "C" void kernel_launch(void* const* d_in, const int* in_sizes, int n_in,
                              void* d_out, int out_size) {
    const float* inputs = (const float*)d_in[0];
    const float* edges  = (const float*)d_in[1];
    const float* W1     = (const float*)d_in[2];
    const float* b1     = (const float*)d_in[3];
    const float* W2     = (const float*)d_in[4];
    const float* b2     = (const float*)d_in[5];
    float* out = (float*)d_out;

    {
        dim3 grid(BN, 4);    // 256 blocks, 16 nodes each (+W2 frag pack)
        precompute_kernel<<<grid, 256>>>(inputs, W1, b1, W2);
    }
    {
        dim3 grid(VN / 2, GY);   // 32 x 13 = 416 blocks, single wave
        edge_mma_kernel<<<grid, 256>>>(inputs, edges, b2, out);
    }
}